// round 9
// baseline (speedup 1.0000x reference)
#include <cuda_runtime.h>
#include <math.h>

// Fixed shapes per reference.
#define B_SZ     16384
#define G_SZ     256
#define NROWS    (B_SZ * G_SZ)        // 4,194,304 (b,g) rows
#define CLS_ROWS 8192                 // flat cls rows: r < 8192 (both anchors)
#define INV_B    (1.0f / 16384.0f)
#define NTHREADS 256
#define NBLOCKS  8192                 // 2,097,152 threads -> exactly 2 rows/thread

// Single-launch reduction state (self-resetting; valid across graph replays).
__device__ float    g_acc = 0.0f;
__device__ unsigned g_cnt = 0u;

__global__ __launch_bounds__(NTHREADS)
void ensemble_loss_kernel(const float4* __restrict__ pred4,
                          const float4* __restrict__ targ4,
                          float* __restrict__ out) {
    const int tid    = blockIdx.x * NTHREADS + threadIdx.x;
    const int stride = NBLOCKS * NTHREADS;

    float acc = 0.0f;

    #pragma unroll 2
    for (int r = tid; r < NROWS; r += stride) {
        // Pred-first plain cached loads — the best-measured (51.712us) config.
        const float4 p0 = pred4[(long long)r * 3 + 0]; // off0,dur0,conf0,cls0_0
        const float4 p1 = pred4[(long long)r * 3 + 1]; // cls0_1,cls0_2,off1,dur1
        const float4 p2 = pred4[(long long)r * 3 + 2]; // conf1,cls1_0,cls1_1,cls1_2
        const float4 t0 = targ4[(long long)r * 2 + 0]; // conf0,cls0,off0,dur0
        const float4 t1 = targ4[(long long)r * 2 + 1]; // conf1,cls1,off1,dur1

        // ---------- anchor 0 ----------
        {
            const float gc = t0.x;              // {0,1}; obj_mask == gc
            const float w  = 0.5f + 0.5f * gc;
            const float dc = gc - p0.z;
            acc += w * dc * dc;

            const float doff = t0.z - p0.x;
            acc += 5.0f * gc * doff * doff;

            // (sqrt(a)-sqrt(b))^2 = a + b - 2*sqrt(a*b)
            const float dd2 = t0.w + p0.y - 2.0f * sqrtf(t0.w * p0.y);
            acc += 5.0f * gc * dd2;

            if (r < CLS_ROWS) {
                const float l0 = gc * p0.w;
                const float l1 = gc * p1.x;
                const float l2 = gc * p1.y;
                const int   idx = (int)(gc * t0.y);
                const float m   = fmaxf(l0, fmaxf(l1, l2));
                const float lse = m + logf(expf(l0 - m) + expf(l1 - m) + expf(l2 - m));
                const float li  = (idx == 0) ? l0 : ((idx == 1) ? l1 : l2);
                acc += lse - li;
            }
        }

        // ---------- anchor 1 ----------
        {
            const float gc = t1.x;
            const float w  = 0.5f + 0.5f * gc;
            const float dc = gc - p2.x;
            acc += w * dc * dc;

            const float doff = t1.z - p1.z;
            acc += 5.0f * gc * doff * doff;

            const float dd2 = t1.w + p1.w - 2.0f * sqrtf(t1.w * p1.w);
            acc += 5.0f * gc * dd2;

            if (r < CLS_ROWS) {
                const float l0 = gc * p2.y;
                const float l1 = gc * p2.z;
                const float l2 = gc * p2.w;
                const int   idx = (int)(gc * t1.y);
                const float m   = fmaxf(l0, fmaxf(l1, l2));
                const float lse = m + logf(expf(l0 - m) + expf(l1 - m) + expf(l2 - m));
                const float li  = (idx == 0) ? l0 : ((idx == 1) ? l1 : l2);
                acc += lse - li;
            }
        }
    }

    // ---- intra-warp reduction ----
    #pragma unroll
    for (int off = 16; off > 0; off >>= 1)
        acc += __shfl_down_sync(0xffffffffu, acc, off);

    // ---- intra-block reduction ----
    __shared__ float smem[8];
    const int lane = threadIdx.x & 31;
    const int warp = threadIdx.x >> 5;
    if (lane == 0) smem[warp] = acc;
    __syncthreads();
    if (warp == 0) {
        acc = (lane < 8) ? smem[lane] : 0.0f;
        #pragma unroll
        for (int off = 4; off > 0; off >>= 1)
            acc += __shfl_down_sync(0xffffffffu, acc, off);

        if (lane == 0) {
            atomicAdd(&g_acc, acc);
            __threadfence();
            const unsigned done = atomicAdd(&g_cnt, 1u);
            if (done == NBLOCKS - 1u) {
                // Last block: all adds visible. Publish and self-reset.
                out[0] = g_acc * INV_B;
                g_acc  = 0.0f;
                g_cnt  = 0u;
            }
        }
    }
}

extern "C" void kernel_launch(void* const* d_in, const int* in_sizes, int n_in,
                              void* d_out, int out_size) {
    const float4* pred4 = (const float4*)d_in[0];
    const float4* targ4 = (const float4*)d_in[1];
    float* out = (float*)d_out;

    ensemble_loss_kernel<<<NBLOCKS, NTHREADS>>>(pred4, targ4, out);
}

// round 11
// speedup vs baseline: 1.0266x; 1.0266x over previous
#include <cuda_runtime.h>
#include <math.h>

// Fixed shapes per reference.
#define B_SZ     16384
#define G_SZ     256
#define NROWS    (B_SZ * G_SZ)        // 4,194,304 (b,g) rows
#define CLS_ROWS 8192                 // flat cls rows: r < 8192 (both anchors)
#define INV_B    (1.0f / 16384.0f)
#define NTHREADS 256
#define NBLOCKS  8192                 // 2,097,152 threads -> exactly 2 rows/thread

// Single-launch reduction state (self-resetting; valid across graph replays).
__device__ float    g_acc = 0.0f;
__device__ unsigned g_cnt = 0u;

__global__ __launch_bounds__(NTHREADS)
void ensemble_loss_kernel(const float4* __restrict__ pred4,
                          const float4* __restrict__ targ4,
                          float* __restrict__ out) {
    const int tid    = blockIdx.x * NTHREADS + threadIdx.x;
    const int stride = NBLOCKS * NTHREADS;

    float acc = 0.0f;

    #pragma unroll 2
    for (int r = tid; r < NROWS; r += stride) {
        // Pred-first plain cached loads — best-measured config (51.712us).
        const float4 p0 = pred4[(long long)r * 3 + 0]; // off0,dur0,conf0,cls0_0
        const float4 p1 = pred4[(long long)r * 3 + 1]; // cls0_1,cls0_2,off1,dur1
        const float4 p2 = pred4[(long long)r * 3 + 2]; // conf1,cls1_0,cls1_1,cls1_2
        const float4 t0 = targ4[(long long)r * 2 + 0]; // conf0,cls0,off0,dur0
        const float4 t1 = targ4[(long long)r * 2 + 1]; // conf1,cls1,off1,dur1

        // ---------- anchor 0 ----------
        {
            const float gc = t0.x;              // {0,1}; obj_mask == gc
            const float w  = 0.5f + 0.5f * gc;
            const float dc = gc - p0.z;
            acc += w * dc * dc;

            const float doff = t0.z - p0.x;
            acc += 5.0f * gc * doff * doff;

            // (sqrt(a)-sqrt(b))^2 = a + b - 2*sqrt(a*b)
            const float dd2 = t0.w + p0.y - 2.0f * sqrtf(t0.w * p0.y);
            acc += 5.0f * gc * dd2;

            if (r < CLS_ROWS) {
                const float l0 = gc * p0.w;
                const float l1 = gc * p1.x;
                const float l2 = gc * p1.y;
                const int   idx = (int)(gc * t0.y);
                const float m   = fmaxf(l0, fmaxf(l1, l2));
                const float lse = m + logf(expf(l0 - m) + expf(l1 - m) + expf(l2 - m));
                const float li  = (idx == 0) ? l0 : ((idx == 1) ? l1 : l2);
                acc += lse - li;
            }
        }

        // ---------- anchor 1 ----------
        {
            const float gc = t1.x;
            const float w  = 0.5f + 0.5f * gc;
            const float dc = gc - p2.x;
            acc += w * dc * dc;

            const float doff = t1.z - p1.z;
            acc += 5.0f * gc * doff * doff;

            const float dd2 = t1.w + p1.w - 2.0f * sqrtf(t1.w * p1.w);
            acc += 5.0f * gc * dd2;

            if (r < CLS_ROWS) {
                const float l0 = gc * p2.y;
                const float l1 = gc * p2.z;
                const float l2 = gc * p2.w;
                const int   idx = (int)(gc * t1.y);
                const float m   = fmaxf(l0, fmaxf(l1, l2));
                const float lse = m + logf(expf(l0 - m) + expf(l1 - m) + expf(l2 - m));
                const float li  = (idx == 0) ? l0 : ((idx == 1) ? l1 : l2);
                acc += lse - li;
            }
        }
    }

    // ---- intra-warp reduction ----
    #pragma unroll
    for (int off = 16; off > 0; off >>= 1)
        acc += __shfl_down_sync(0xffffffffu, acc, off);

    // ---- intra-block reduction ----
    __shared__ float smem[8];
    const int lane = threadIdx.x & 31;
    const int warp = threadIdx.x >> 5;
    if (lane == 0) smem[warp] = acc;
    __syncthreads();
    if (warp == 0) {
        acc = (lane < 8) ? smem[lane] : 0.0f;
        #pragma unroll
        for (int off = 4; off > 0; off >>= 1)
            acc += __shfl_down_sync(0xffffffffu, acc, off);

        if (lane == 0) {
            atomicAdd(&g_acc, acc);
            __threadfence();
            const unsigned done = atomicAdd(&g_cnt, 1u);
            if (done == NBLOCKS - 1u) {
                // Last block: all adds visible. Publish and self-reset.
                out[0] = g_acc * INV_B;
                g_acc  = 0.0f;
                g_cnt  = 0u;
            }
        }
    }
}

extern "C" void kernel_launch(void* const* d_in, const int* in_sizes, int n_in,
                              void* d_out, int out_size) {
    const float4* pred4 = (const float4*)d_in[0];
    const float4* targ4 = (const float4*)d_in[1];
    float* out = (float*)d_out;

    ensemble_loss_kernel<<<NBLOCKS, NTHREADS>>>(pred4, targ4, out);
}